// round 11
// baseline (speedup 1.0000x reference)
#include <cuda_runtime.h>

#define EPS 1e-5f

// Device-global scratch (no allocations allowed). All statically zero-initialized.
__device__ float4 gF1[256];          // (A1, B1, a1, b13)
__device__ float4 gF2[256];          // (A2, B2, a2, b23)
__device__ float  gB21[256];
__device__ float  gB11[256];
__device__ float  gT[32 * 3136];
__device__ int    gAny3, gAny1;      // set (idempotently) only if corrections exist
__device__ int    gCnt3[256], gCnt1[256];
__device__ int4   gL3[256 * 2304];   // per-out-channel list: (cin, k, d, 0), d=sign(w)-1
__device__ int4   gL1[256 * 256];    // per-out-channel list: (cin, 0, d, 0)

__device__ __forceinline__ float sgnf(float v) {
    return (float)((v > 0.f) - (v < 0.f));
}

// Per-out-channel weight scale (mean|w|) -> fused BN constants; plus per-channel
// sparse lists of weights whose sign is not +1 (exact handling, expected empty).
// Fully idempotent: fixed slots overwritten each run; gAny* only written when set.
__global__ __launch_bounds__(256) void kSC(
    const float* __restrict__ w3, const float* __restrict__ w1,
    const float* __restrict__ b11, const float* __restrict__ b12, const float* __restrict__ b13,
    const float* __restrict__ b21, const float* __restrict__ b22, const float* __restrict__ b23,
    const float* __restrict__ g1,  const float* __restrict__ be1, const float* __restrict__ m1, const float* __restrict__ v1,
    const float* __restrict__ g2,  const float* __restrict__ be2, const float* __restrict__ m2, const float* __restrict__ v2,
    const float* __restrict__ a1,  const float* __restrict__ a2)
{
    __shared__ float red[256];
    __shared__ int   scnt;
    int b = blockIdx.x, t = threadIdx.x;
    if (t == 0) scnt = 0;
    __syncthreads();

    float sum = 0.f;
    if (b < 256) {
        int o = b;
        const float* wp = w3 + (o * 256 + t) * 9;
        #pragma unroll
        for (int k = 0; k < 9; k++) {
            float w = wp[k];
            sum += fabsf(w);
            if (w <= 0.f) {
                int idx = atomicAdd(&scnt, 1);
                gL3[o * 2304 + idx] = make_int4(t, k, (w == 0.f) ? -1 : -2, 0);
            }
        }
    } else {
        int o = b - 256;
        float w = w1[o * 256 + t];
        sum = fabsf(w);
        if (w <= 0.f) {
            int idx = atomicAdd(&scnt, 1);
            gL1[o * 256 + idx] = make_int4(t, 0, (w == 0.f) ? -1 : -2, 0);
        }
    }
    red[t] = sum;
    __syncthreads();
    #pragma unroll
    for (int s = 128; s > 0; s >>= 1) {
        if (t < s) red[t] += red[t + s];
        __syncthreads();
    }
    if (t == 0) {
        if (b < 256) {
            int c = b;
            float s3   = red[0] * (1.f / 2304.f);
            float inv1 = g1[c] / sqrtf(v1[c] + EPS);
            gF1[c]  = make_float4(inv1 * s3, be1[c] - m1[c] * inv1 + b12[c], a1[c], b13[c]);
            gB21[c] = b21[c];
            gB11[c] = b11[c];
            gCnt3[c] = scnt;
            if (scnt > 0) gAny3 = 1;          // idempotent
        } else {
            int c = b - 256;
            float s1   = red[0] * (1.f / 256.f);
            float inv2 = g2[c] / sqrtf(v2[c] + EPS);
            gF2[c] = make_float4(inv2 * s1, be2[c] - m2[c] * inv2 + b22[c], a2[c], b23[c]);
            gCnt1[c] = scnt;
            if (scnt > 0) gAny1 = 1;          // idempotent
        }
    }
}

// T pass: per-pixel channel-sum of sign(x + b11). All loads LDG.128.
// thread = (float4-pixel v, channel-group grp): 32 groups x 8 channels.
__global__ __launch_bounds__(256) void kT(const float* __restrict__ x,
                                          const float* __restrict__ b11)
{
    __shared__ int4 red4[256];
    const int t = threadIdx.x, v = t & 7, grp = t >> 3;
    const int n = blockIdx.y, p0 = blockIdx.x * 32;
    const float4* xb4 = (const float4*)(x + (size_t)n * 802816 + p0) + v;

    int4 acc = make_int4(0, 0, 0, 0);
    #pragma unroll
    for (int i = 0; i < 8; i++) {
        int c = grp * 8 + i;
        float4 q = __ldg(xb4 + (size_t)c * 784);   // 3136/4
        float bc = __ldg(b11 + c);
        acc.x += (q.x + bc > 0.f) - (q.x + bc < 0.f);
        acc.y += (q.y + bc > 0.f) - (q.y + bc < 0.f);
        acc.z += (q.z + bc > 0.f) - (q.z + bc < 0.f);
        acc.w += (q.w + bc > 0.f) - (q.w + bc < 0.f);
    }
    red4[grp * 8 + v] = acc;
    __syncthreads();
    if (t < 32) {
        const int* r = (const int*)red4;
        int s = 0;
        #pragma unroll
        for (int g = 0; g < 32; g++) s += r[g * 32 + t];
        gT[n * 3136 + p0 + t] = (float)s;
    }
}

// Main pass: 32 pixels x 256 channels per block; 512 threads, 4 channels/thread.
// out1 register-resident (smem tile written only on the cold correction path).
__global__ __launch_bounds__(512, 2) void kMain(const float* __restrict__ x,
                                                float* __restrict__ out)
{
    __shared__ float4 o1cold[256 * 8];     // 32 KB, used only if gAny1
    __shared__ int4   red4[512];
    __shared__ float  Ssm[32], T2sm[32];
    const int t = threadIdx.x, v = t & 7, grp = t >> 3;   // grp 0..63
    // Reverse block order so wave 1 re-reads the x regions kT touched last (L2 reuse).
    const int n  = 31 - blockIdx.y;
    const int p0 = 3104 - blockIdx.x * 32;

    // S = 3x3 zero-padded box-sum of T for the block's 32 pixels.
    if (t < 32) {
        int p = p0 + t, h = p / 56, w0 = p % 56;
        const float* Tb = gT + n * 3136;
        float s = 0.f;
        #pragma unroll
        for (int dy = -1; dy <= 1; dy++) {
            int y = h + dy;
            if (y >= 0 && y < 56) {
                int rb = y * 56;
                #pragma unroll
                for (int dx = -1; dx <= 1; dx++) {
                    int xx = w0 + dx;
                    if (xx >= 0 && xx < 56) s += Tb[rb + xx];
                }
            }
        }
        Ssm[t] = s;
    }
    __syncthreads();

    const int any3 = gAny3, any1 = gAny1;

    const float4* xb4 = (const float4*)(x + (size_t)n * 802816 + p0) + v;
    const float4  Sv4 = ((const float4*)Ssm)[v];

    // Phase 1: out1 per (channel, my 4 pixels) in registers; accumulate sign-sum T2.
    float4 o1r[4];
    int4 t2 = make_int4(0, 0, 0, 0);
    #pragma unroll
    for (int i = 0; i < 4; i++) {
        int c = grp * 4 + i;
        float4 F  = __ldg(gF1 + c);
        float4 xv = __ldg(xb4 + (size_t)c * 784);
        float4 Sc = Sv4;
        if (any3) {                              // rare exact-correction path
            int cnt = gCnt3[c];
            #pragma unroll
            for (int k = 0; k < 4; k++) {
                float corr = 0.f;
                int p = p0 + v * 4 + k, h = p / 56, w0 = p % 56;
                for (int e = 0; e < cnt; e++) {
                    int4 E = gL3[c * 2304 + e];
                    int dy = E.y / 3 - 1, dx = E.y % 3 - 1;
                    int y = h + dy, xx = w0 + dx;
                    if (y >= 0 && y < 56 && xx >= 0 && xx < 56) {
                        float vv = x[(size_t)n * 802816 + (size_t)E.x * 3136 + y * 56 + xx] + gB11[E.x];
                        corr += (float)E.z * sgnf(vv);
                    }
                }
                ((float*)&Sc)[k] += corr;
            }
        }
        float b21c = __ldg(gB21 + c);
        float4 o1;
        float pre;
        pre = __fmaf_rn(F.x, Sc.x, xv.x + F.y); o1.x = (pre > 0.f ? pre : F.z * pre) + F.w;
        pre = __fmaf_rn(F.x, Sc.y, xv.y + F.y); o1.y = (pre > 0.f ? pre : F.z * pre) + F.w;
        pre = __fmaf_rn(F.x, Sc.z, xv.z + F.y); o1.z = (pre > 0.f ? pre : F.z * pre) + F.w;
        pre = __fmaf_rn(F.x, Sc.w, xv.w + F.y); o1.w = (pre > 0.f ? pre : F.z * pre) + F.w;
        o1r[i] = o1;
        if (any1) o1cold[c * 8 + v] = o1;        // cold path only
        t2.x += (o1.x + b21c > 0.f) - (o1.x + b21c < 0.f);
        t2.y += (o1.y + b21c > 0.f) - (o1.y + b21c < 0.f);
        t2.z += (o1.z + b21c > 0.f) - (o1.z + b21c < 0.f);
        t2.w += (o1.w + b21c > 0.f) - (o1.w + b21c < 0.f);
    }
    red4[t] = t2;
    __syncthreads();
    if (t < 32) {
        const int* r = (const int*)red4;
        int s = 0;
        #pragma unroll
        for (int g = 0; g < 64; g++) s += r[g * 32 + t];
        T2sm[t] = (float)s;
    }
    __syncthreads();

    const float4 T2v4 = ((const float4*)T2sm)[v];
    float4* ob4 = (float4*)(out + (size_t)n * 802816 + p0) + v;

    // Phase 2: out2 from register-resident out1 + T2; streaming 128-bit stores.
    #pragma unroll
    for (int i = 0; i < 4; i++) {
        int c = grp * 4 + i;
        float4 F  = __ldg(gF2 + c);
        float4 o1 = o1r[i];
        float4 Tv = T2v4;
        if (any1) {                              // rare exact-correction path
            int cnt = gCnt1[c];
            #pragma unroll
            for (int k = 0; k < 4; k++) {
                float corr = 0.f;
                int p = v * 4 + k;
                for (int e = 0; e < cnt; e++) {
                    int4 E = gL1[c * 256 + e];
                    float u = ((const float*)o1cold)[E.x * 32 + p] + gB21[E.x];
                    corr += (float)E.z * sgnf(u);
                }
                ((float*)&Tv)[k] += corr;
            }
        }
        float4 o2;
        float pre;
        pre = __fmaf_rn(F.x, Tv.x, o1.x + F.y); o2.x = (pre > 0.f ? pre : F.z * pre) + F.w;
        pre = __fmaf_rn(F.x, Tv.y, o1.y + F.y); o2.y = (pre > 0.f ? pre : F.z * pre) + F.w;
        pre = __fmaf_rn(F.x, Tv.z, o1.z + F.y); o2.z = (pre > 0.f ? pre : F.z * pre) + F.w;
        pre = __fmaf_rn(F.x, Tv.w, o1.w + F.y); o2.w = (pre > 0.f ? pre : F.z * pre) + F.w;
        __stcs(ob4 + (size_t)c * 784, o2);
    }
}

extern "C" void kernel_launch(void* const* d_in, const int* in_sizes, int n_in,
                              void* d_out, int out_size) {
    const float* x   = (const float*)d_in[0];
    const float* w3  = (const float*)d_in[1];
    const float* w1  = (const float*)d_in[2];
    const float* b11 = (const float*)d_in[3];
    const float* b12 = (const float*)d_in[4];
    const float* b13 = (const float*)d_in[5];
    const float* b21 = (const float*)d_in[6];
    const float* b22 = (const float*)d_in[7];
    const float* b23 = (const float*)d_in[8];
    const float* g1  = (const float*)d_in[9];
    const float* be1 = (const float*)d_in[10];
    const float* m1  = (const float*)d_in[11];
    const float* v1  = (const float*)d_in[12];
    const float* g2  = (const float*)d_in[13];
    const float* be2 = (const float*)d_in[14];
    const float* m2  = (const float*)d_in[15];
    const float* v2  = (const float*)d_in[16];
    const float* a1  = (const float*)d_in[17];
    const float* a2  = (const float*)d_in[18];
    float* out = (float*)d_out;

    kSC<<<512, 256>>>(w3, w1, b11, b12, b13, b21, b22, b23,
                      g1, be1, m1, v1, g2, be2, m2, v2, a1, a2);
    kT<<<dim3(98, 32), 256>>>(x, b11);
    kMain<<<dim3(98, 32), 512>>>(x, out);
}